// round 14
// baseline (speedup 1.0000x reference)
#include <cuda_runtime.h>

// out[p,:] = sum_{k in row p} PHI[k] * ctrl_pts[Jm[k],:]
// CONVERGED champion (validated over 13 rounds):
//   - ctrl repacked to 16B-aligned float4 table: 1 gather = 1 LDG.128 = one
//     32B sector = one L1tex wavefront (12B raw layout costs ~2.5x more)
//   - 8 lanes/point, 4 points/warp, MLP 8 __ldcg gathers (L2-only, no L1
//     fills), __ldcs instruction-contiguous streaming loads, block 128,
//     natural occupancy, simple epilogue.
//   - Measured: L1tex 92% + LTS 83% dual-saturated = the 64M-random-gather
//     wavefront floor. All structural alternatives measured slower.
// R14: eval kernel byte-identical; pack prologue vectorized (3 coalesced
// float4 loads -> 4 float4 stores per thread) to its 14MB DRAM floor.

#define MAX_CTRL 524288

__device__ __align__(16) float4 g_ctrl4[MAX_CTRL];   // 8 MB static scratch

__global__ __launch_bounds__(256)
void pack_ctrl_kernel(const float* __restrict__ ctrl, int n_ctrl)
{
    const int q      = blockIdx.x * blockDim.x + threadIdx.x;
    const int nquads = n_ctrl >> 2;          // 4 entries per thread
    if (q < nquads) {
        const float4* __restrict__ src = reinterpret_cast<const float4*>(ctrl) + 3 * q;
        const float4 a = src[0];   // x0 y0 z0 x1
        const float4 b = src[1];   // y1 z1 x2 y2
        const float4 c = src[2];   // z2 x3 y3 z3
        const int base = 4 * q;
        g_ctrl4[base + 0] = make_float4(a.x, a.y, a.z, 0.f);
        g_ctrl4[base + 1] = make_float4(a.w, b.x, b.y, 0.f);
        g_ctrl4[base + 2] = make_float4(b.z, b.w, c.x, 0.f);
        g_ctrl4[base + 3] = make_float4(c.y, c.z, c.w, 0.f);
    } else {
        // tail entries (n_ctrl not a multiple of 4): threads nquads..nquads+2
        const int t = 4 * nquads + (q - nquads);
        if (t < n_ctrl) {
            const float* cc = ctrl + 3u * (unsigned)t;
            g_ctrl4[t] = make_float4(cc[0], cc[1], cc[2], 0.f);
        }
    }
}

__global__ __launch_bounds__(128)
void thb_eval_packed_kernel(const float* __restrict__ phi,
                            const int*   __restrict__ jm,
                            const int*   __restrict__ cum,
                            float*       __restrict__ out,
                            int num_pts)
{
    const int tid  = blockIdx.x * blockDim.x + threadIdx.x;
    const int lane = threadIdx.x & 31;
    const int l8   = lane & 7;                       // lane within 8-lane group
    const int p    = (tid >> 5) * 4 + (lane >> 3);   // this group's point

    int start = 0, end = 0;
    if (p < num_pts) {
        start = (p == 0) ? 0 : __ldg(&cum[p - 1]);
        end   = __ldg(&cum[p]);
    }
    const int n = end - start;

    float sx = 0.f, sy = 0.f, sz = 0.f;

    if (n == 64 && ((start & 3) == 0)) {
        // Instruction-contiguous streaming: load i covers row entries
        // [32*i + 4*l8, +4), so each LDG.128 reads whole 128B lines across
        // the 8-lane group.
        const float4* __restrict__ p4 = reinterpret_cast<const float4*>(phi + start);
        const int4*   __restrict__ j4 = reinterpret_cast<const int4*>(jm + start);
        const float4 w0 = __ldcs(&p4[l8]);
        const float4 w1 = __ldcs(&p4[l8 + 8]);
        const int4   j0 = __ldcs(&j4[l8]);
        const int4   j1 = __ldcs(&j4[l8 + 8]);

        // 8 independent gathers, L2-only (no L1 allocation) -> MLP 8
        const float4 c0 = __ldcg(&g_ctrl4[j0.x]);
        const float4 c1 = __ldcg(&g_ctrl4[j0.y]);
        const float4 c2 = __ldcg(&g_ctrl4[j0.z]);
        const float4 c3 = __ldcg(&g_ctrl4[j0.w]);
        const float4 c4 = __ldcg(&g_ctrl4[j1.x]);
        const float4 c5 = __ldcg(&g_ctrl4[j1.y]);
        const float4 c6 = __ldcg(&g_ctrl4[j1.z]);
        const float4 c7 = __ldcg(&g_ctrl4[j1.w]);

        sx = fmaf(w0.x, c0.x, sx); sy = fmaf(w0.x, c0.y, sy); sz = fmaf(w0.x, c0.z, sz);
        sx = fmaf(w0.y, c1.x, sx); sy = fmaf(w0.y, c1.y, sy); sz = fmaf(w0.y, c1.z, sz);
        sx = fmaf(w0.z, c2.x, sx); sy = fmaf(w0.z, c2.y, sy); sz = fmaf(w0.z, c2.z, sz);
        sx = fmaf(w0.w, c3.x, sx); sy = fmaf(w0.w, c3.y, sy); sz = fmaf(w0.w, c3.z, sz);
        sx = fmaf(w1.x, c4.x, sx); sy = fmaf(w1.x, c4.y, sy); sz = fmaf(w1.x, c4.z, sz);
        sx = fmaf(w1.y, c5.x, sx); sy = fmaf(w1.y, c5.y, sy); sz = fmaf(w1.y, c5.z, sz);
        sx = fmaf(w1.z, c6.x, sx); sy = fmaf(w1.z, c6.y, sy); sz = fmaf(w1.z, c6.z, sz);
        sx = fmaf(w1.w, c7.x, sx); sy = fmaf(w1.w, c7.y, sy); sz = fmaf(w1.w, c7.z, sz);
    } else {
        for (int k = start + l8; k < end; k += 8) {
            const float w   = phi[k];
            const float4 cc = __ldcg(&g_ctrl4[jm[k]]);
            sx = fmaf(w, cc.x, sx);
            sy = fmaf(w, cc.y, sy);
            sz = fmaf(w, cc.z, sz);
        }
    }

    // butterfly reduce within each 8-lane group
    #pragma unroll
    for (int off = 4; off > 0; off >>= 1) {
        sx += __shfl_xor_sync(0xFFFFFFFFu, sx, off);
        sy += __shfl_xor_sync(0xFFFFFFFFu, sy, off);
        sz += __shfl_xor_sync(0xFFFFFFFFu, sz, off);
    }

    if (l8 == 0 && p < num_pts) {
        const unsigned o = 3u * (unsigned)p;
        out[o + 0] = sx;
        out[o + 1] = sy;
        out[o + 2] = sz;
    }
}

// Generic fallback for oversized control tables (no packing possible).
__global__ __launch_bounds__(256)
void thb_eval_raw_kernel(const float* __restrict__ ctrl,
                         const float* __restrict__ phi,
                         const int*   __restrict__ jm,
                         const int*   __restrict__ cum,
                         float*       __restrict__ out,
                         int num_pts)
{
    const int warp = (int)((blockIdx.x * (unsigned)blockDim.x + threadIdx.x) >> 5);
    if (warp >= num_pts) return;
    const int lane = threadIdx.x & 31;

    const int start = (warp == 0) ? 0 : cum[warp - 1];
    const int end   = cum[warp];

    float sx = 0.f, sy = 0.f, sz = 0.f;
    for (int k = start + lane; k < end; k += 32) {
        const float w = phi[k];
        const float* c = ctrl + 3u * (unsigned)jm[k];
        sx = fmaf(w, c[0], sx);
        sy = fmaf(w, c[1], sy);
        sz = fmaf(w, c[2], sz);
    }

    #pragma unroll
    for (int off = 16; off > 0; off >>= 1) {
        sx += __shfl_xor_sync(0xFFFFFFFFu, sx, off);
        sy += __shfl_xor_sync(0xFFFFFFFFu, sy, off);
        sz += __shfl_xor_sync(0xFFFFFFFFu, sz, off);
    }

    if (lane == 0) {
        const unsigned o = 3u * (unsigned)warp;
        out[o + 0] = sx;
        out[o + 1] = sy;
        out[o + 2] = sz;
    }
}

extern "C" void kernel_launch(void* const* d_in, const int* in_sizes, int n_in,
                              void* d_out, int out_size)
{
    const float* ctrl = (const float*)d_in[0];   // [N_CTRL, 3] f32
    const float* phi  = (const float*)d_in[1];   // [TOTAL] f32
    const int*   jm   = (const int*)d_in[2];     // [TOTAL] i32
    const int*   cum  = (const int*)d_in[3];     // [P] i32 inclusive row ends
    float*       out  = (float*)d_out;           // [P, 3] f32

    const int n_ctrl  = in_sizes[0] / 3;
    const int num_pts = in_sizes[3];

    if (n_ctrl <= MAX_CTRL) {
        const int nquads       = n_ctrl >> 2;
        const int pack_threads = nquads + (n_ctrl - 4 * nquads);  // quads + tail
        pack_ctrl_kernel<<<(pack_threads + 255) / 256, 256>>>(ctrl, n_ctrl);
        // 4 points/warp, 4 warps/block -> 16 points per block (validated optimum)
        const int blocks = (num_pts + 15) / 16;
        thb_eval_packed_kernel<<<blocks, 128>>>(phi, jm, cum, out, num_pts);
    } else {
        const int threads = 256;
        const long long total_threads = (long long)num_pts * 32;
        const int blocks = (int)((total_threads + threads - 1) / threads);
        thb_eval_raw_kernel<<<blocks, threads>>>(ctrl, phi, jm, cum, out, num_pts);
    }
}

// round 15
// speedup vs baseline: 1.0151x; 1.0151x over previous
#include <cuda_runtime.h>

// out[p,:] = sum_{k in row p} PHI[k] * ctrl_pts[Jm[k],:]
// FINAL champion (reproduced 246.3us at R10 and R13; 14 rounds of evidence):
//   - ctrl repacked to 16B-aligned float4 table: 1 gather = 1 LDG.128 = one
//     32B sector = one L1tex wavefront (12B raw layout costs ~2.5x more)
//   - 8 lanes/point, 4 points/warp: MLP 8 __ldcg gathers (MLP 16 regressed —
//     ptxas interleaves; MLP 2 regressed — latency-exposed)
//   - __ldcg gathers: 8MB table is L2-resident; skip useless L1 line fills
//   - __ldcs instruction-contiguous streaming loads (full 128B lines/instr)
//   - block 128 (64 and 256 measured slower), natural occupancy (reg-cap
//     regressed), non-persistent (persistent regressed), simple epilogue
//     (shuffle-packed stores regressed), simple scalar pack kernel
//     (vectorized pack regressed: 3-stride f4 loads decoalesce).
// Measured: L1tex 92% + LTS 83% dual-saturated = the 64M-random-gather
// wavefront floor; residual ~8% gap = B300 between-SM spread floor.

#define MAX_CTRL 524288

__device__ __align__(16) float4 g_ctrl4[MAX_CTRL];   // 8 MB static scratch

__global__ __launch_bounds__(256)
void pack_ctrl_kernel(const float* __restrict__ ctrl, int n_ctrl)
{
    int i = blockIdx.x * blockDim.x + threadIdx.x;
    if (i < n_ctrl) {
        const float* c = ctrl + 3u * (unsigned)i;
        g_ctrl4[i] = make_float4(c[0], c[1], c[2], 0.0f);
    }
}

__global__ __launch_bounds__(128)
void thb_eval_packed_kernel(const float* __restrict__ phi,
                            const int*   __restrict__ jm,
                            const int*   __restrict__ cum,
                            float*       __restrict__ out,
                            int num_pts)
{
    const int tid  = blockIdx.x * blockDim.x + threadIdx.x;
    const int lane = threadIdx.x & 31;
    const int l8   = lane & 7;                       // lane within 8-lane group
    const int p    = (tid >> 5) * 4 + (lane >> 3);   // this group's point

    int start = 0, end = 0;
    if (p < num_pts) {
        start = (p == 0) ? 0 : __ldg(&cum[p - 1]);
        end   = __ldg(&cum[p]);
    }
    const int n = end - start;

    float sx = 0.f, sy = 0.f, sz = 0.f;

    if (n == 64 && ((start & 3) == 0)) {
        // Instruction-contiguous streaming: load i covers row entries
        // [32*i + 4*l8, +4), so each LDG.128 reads whole 128B lines across
        // the 8-lane group.
        const float4* __restrict__ p4 = reinterpret_cast<const float4*>(phi + start);
        const int4*   __restrict__ j4 = reinterpret_cast<const int4*>(jm + start);
        const float4 w0 = __ldcs(&p4[l8]);
        const float4 w1 = __ldcs(&p4[l8 + 8]);
        const int4   j0 = __ldcs(&j4[l8]);
        const int4   j1 = __ldcs(&j4[l8 + 8]);

        // 8 independent gathers, L2-only (no L1 allocation) -> MLP 8
        const float4 c0 = __ldcg(&g_ctrl4[j0.x]);
        const float4 c1 = __ldcg(&g_ctrl4[j0.y]);
        const float4 c2 = __ldcg(&g_ctrl4[j0.z]);
        const float4 c3 = __ldcg(&g_ctrl4[j0.w]);
        const float4 c4 = __ldcg(&g_ctrl4[j1.x]);
        const float4 c5 = __ldcg(&g_ctrl4[j1.y]);
        const float4 c6 = __ldcg(&g_ctrl4[j1.z]);
        const float4 c7 = __ldcg(&g_ctrl4[j1.w]);

        sx = fmaf(w0.x, c0.x, sx); sy = fmaf(w0.x, c0.y, sy); sz = fmaf(w0.x, c0.z, sz);
        sx = fmaf(w0.y, c1.x, sx); sy = fmaf(w0.y, c1.y, sy); sz = fmaf(w0.y, c1.z, sz);
        sx = fmaf(w0.z, c2.x, sx); sy = fmaf(w0.z, c2.y, sy); sz = fmaf(w0.z, c2.z, sz);
        sx = fmaf(w0.w, c3.x, sx); sy = fmaf(w0.w, c3.y, sy); sz = fmaf(w0.w, c3.z, sz);
        sx = fmaf(w1.x, c4.x, sx); sy = fmaf(w1.x, c4.y, sy); sz = fmaf(w1.x, c4.z, sz);
        sx = fmaf(w1.y, c5.x, sx); sy = fmaf(w1.y, c5.y, sy); sz = fmaf(w1.y, c5.z, sz);
        sx = fmaf(w1.z, c6.x, sx); sy = fmaf(w1.z, c6.y, sy); sz = fmaf(w1.z, c6.z, sz);
        sx = fmaf(w1.w, c7.x, sx); sy = fmaf(w1.w, c7.y, sy); sz = fmaf(w1.w, c7.z, sz);
    } else {
        for (int k = start + l8; k < end; k += 8) {
            const float w   = phi[k];
            const float4 cc = __ldcg(&g_ctrl4[jm[k]]);
            sx = fmaf(w, cc.x, sx);
            sy = fmaf(w, cc.y, sy);
            sz = fmaf(w, cc.z, sz);
        }
    }

    // butterfly reduce within each 8-lane group
    #pragma unroll
    for (int off = 4; off > 0; off >>= 1) {
        sx += __shfl_xor_sync(0xFFFFFFFFu, sx, off);
        sy += __shfl_xor_sync(0xFFFFFFFFu, sy, off);
        sz += __shfl_xor_sync(0xFFFFFFFFu, sz, off);
    }

    if (l8 == 0 && p < num_pts) {
        const unsigned o = 3u * (unsigned)p;
        out[o + 0] = sx;
        out[o + 1] = sy;
        out[o + 2] = sz;
    }
}

// Generic fallback for oversized control tables (no packing possible).
__global__ __launch_bounds__(256)
void thb_eval_raw_kernel(const float* __restrict__ ctrl,
                         const float* __restrict__ phi,
                         const int*   __restrict__ jm,
                         const int*   __restrict__ cum,
                         float*       __restrict__ out,
                         int num_pts)
{
    const int warp = (int)((blockIdx.x * (unsigned)blockDim.x + threadIdx.x) >> 5);
    if (warp >= num_pts) return;
    const int lane = threadIdx.x & 31;

    const int start = (warp == 0) ? 0 : cum[warp - 1];
    const int end   = cum[warp];

    float sx = 0.f, sy = 0.f, sz = 0.f;
    for (int k = start + lane; k < end; k += 32) {
        const float w = phi[k];
        const float* c = ctrl + 3u * (unsigned)jm[k];
        sx = fmaf(w, c[0], sx);
        sy = fmaf(w, c[1], sy);
        sz = fmaf(w, c[2], sz);
    }

    #pragma unroll
    for (int off = 16; off > 0; off >>= 1) {
        sx += __shfl_xor_sync(0xFFFFFFFFu, sx, off);
        sy += __shfl_xor_sync(0xFFFFFFFFu, sy, off);
        sz += __shfl_xor_sync(0xFFFFFFFFu, sz, off);
    }

    if (lane == 0) {
        const unsigned o = 3u * (unsigned)warp;
        out[o + 0] = sx;
        out[o + 1] = sy;
        out[o + 2] = sz;
    }
}

extern "C" void kernel_launch(void* const* d_in, const int* in_sizes, int n_in,
                              void* d_out, int out_size)
{
    const float* ctrl = (const float*)d_in[0];   // [N_CTRL, 3] f32
    const float* phi  = (const float*)d_in[1];   // [TOTAL] f32
    const int*   jm   = (const int*)d_in[2];     // [TOTAL] i32
    const int*   cum  = (const int*)d_in[3];     // [P] i32 inclusive row ends
    float*       out  = (float*)d_out;           // [P, 3] f32

    const int n_ctrl  = in_sizes[0] / 3;
    const int num_pts = in_sizes[3];

    if (n_ctrl <= MAX_CTRL) {
        pack_ctrl_kernel<<<(n_ctrl + 255) / 256, 256>>>(ctrl, n_ctrl);
        // 4 points/warp, 4 warps/block -> 16 points per block (validated optimum)
        const int blocks = (num_pts + 15) / 16;
        thb_eval_packed_kernel<<<blocks, 128>>>(phi, jm, cum, out, num_pts);
    } else {
        const int threads = 256;
        const long long total_threads = (long long)num_pts * 32;
        const int blocks = (int)((total_threads + threads - 1) / threads);
        thb_eval_raw_kernel<<<blocks, threads>>>(ctrl, phi, jm, cum, out, num_pts);
    }
}

// round 16
// speedup vs baseline: 1.0155x; 1.0004x over previous
#include <cuda_runtime.h>

// out[p,:] = sum_{k in row p} PHI[k] * ctrl_pts[Jm[k],:]
// FINAL champion — reproduced 246.3us three times (R10/R13/R15), sigma<0.1%.
// 395us (naive warp/point) -> 246us over 15 measured rounds:
//   - ctrl repacked to 16B-aligned float4 table: 1 gather = 1 LDG.128 = one
//     32B sector = one L1tex wavefront (raw 12B layout costs ~2.5x)
//   - 8 lanes/point, 4 points/warp, MLP 8 __ldcg gathers (L2-resident 8MB
//     table, no L1 fills), __ldcs instruction-contiguous streaming loads
//   - block 128, natural occupancy, non-persistent, direct stores
// Every alternative on every axis (lanes/point 32|4, MLP 2|16, block 64|256,
// forced occupancy, persistence, shuffle-packed stores, stcs, load hoisting,
// vectorized pack) measured equal or slower.
// Bound: L1tex 92% + LTS 83% dual-saturated = 64M-random-gather wavefront
// floor (432K cyc/SM); residual ~8% = B300 between-SM spread floor.

#define MAX_CTRL 524288

__device__ __align__(16) float4 g_ctrl4[MAX_CTRL];   // 8 MB static scratch

__global__ __launch_bounds__(256)
void pack_ctrl_kernel(const float* __restrict__ ctrl, int n_ctrl)
{
    int i = blockIdx.x * blockDim.x + threadIdx.x;
    if (i < n_ctrl) {
        const float* c = ctrl + 3u * (unsigned)i;
        g_ctrl4[i] = make_float4(c[0], c[1], c[2], 0.0f);
    }
}

__global__ __launch_bounds__(128)
void thb_eval_packed_kernel(const float* __restrict__ phi,
                            const int*   __restrict__ jm,
                            const int*   __restrict__ cum,
                            float*       __restrict__ out,
                            int num_pts)
{
    const int tid  = blockIdx.x * blockDim.x + threadIdx.x;
    const int lane = threadIdx.x & 31;
    const int l8   = lane & 7;                       // lane within 8-lane group
    const int p    = (tid >> 5) * 4 + (lane >> 3);   // this group's point

    int start = 0, end = 0;
    if (p < num_pts) {
        start = (p == 0) ? 0 : __ldg(&cum[p - 1]);
        end   = __ldg(&cum[p]);
    }
    const int n = end - start;

    float sx = 0.f, sy = 0.f, sz = 0.f;

    if (n == 64 && ((start & 3) == 0)) {
        // Instruction-contiguous streaming: load i covers row entries
        // [32*i + 4*l8, +4), so each LDG.128 reads whole 128B lines across
        // the 8-lane group.
        const float4* __restrict__ p4 = reinterpret_cast<const float4*>(phi + start);
        const int4*   __restrict__ j4 = reinterpret_cast<const int4*>(jm + start);
        const float4 w0 = __ldcs(&p4[l8]);
        const float4 w1 = __ldcs(&p4[l8 + 8]);
        const int4   j0 = __ldcs(&j4[l8]);
        const int4   j1 = __ldcs(&j4[l8 + 8]);

        // 8 independent gathers, L2-only (no L1 allocation) -> MLP 8
        const float4 c0 = __ldcg(&g_ctrl4[j0.x]);
        const float4 c1 = __ldcg(&g_ctrl4[j0.y]);
        const float4 c2 = __ldcg(&g_ctrl4[j0.z]);
        const float4 c3 = __ldcg(&g_ctrl4[j0.w]);
        const float4 c4 = __ldcg(&g_ctrl4[j1.x]);
        const float4 c5 = __ldcg(&g_ctrl4[j1.y]);
        const float4 c6 = __ldcg(&g_ctrl4[j1.z]);
        const float4 c7 = __ldcg(&g_ctrl4[j1.w]);

        sx = fmaf(w0.x, c0.x, sx); sy = fmaf(w0.x, c0.y, sy); sz = fmaf(w0.x, c0.z, sz);
        sx = fmaf(w0.y, c1.x, sx); sy = fmaf(w0.y, c1.y, sy); sz = fmaf(w0.y, c1.z, sz);
        sx = fmaf(w0.z, c2.x, sx); sy = fmaf(w0.z, c2.y, sy); sz = fmaf(w0.z, c2.z, sz);
        sx = fmaf(w0.w, c3.x, sx); sy = fmaf(w0.w, c3.y, sy); sz = fmaf(w0.w, c3.z, sz);
        sx = fmaf(w1.x, c4.x, sx); sy = fmaf(w1.x, c4.y, sy); sz = fmaf(w1.x, c4.z, sz);
        sx = fmaf(w1.y, c5.x, sx); sy = fmaf(w1.y, c5.y, sy); sz = fmaf(w1.y, c5.z, sz);
        sx = fmaf(w1.z, c6.x, sx); sy = fmaf(w1.z, c6.y, sy); sz = fmaf(w1.z, c6.z, sz);
        sx = fmaf(w1.w, c7.x, sx); sy = fmaf(w1.w, c7.y, sy); sz = fmaf(w1.w, c7.z, sz);
    } else {
        for (int k = start + l8; k < end; k += 8) {
            const float w   = phi[k];
            const float4 cc = __ldcg(&g_ctrl4[jm[k]]);
            sx = fmaf(w, cc.x, sx);
            sy = fmaf(w, cc.y, sy);
            sz = fmaf(w, cc.z, sz);
        }
    }

    // butterfly reduce within each 8-lane group
    #pragma unroll
    for (int off = 4; off > 0; off >>= 1) {
        sx += __shfl_xor_sync(0xFFFFFFFFu, sx, off);
        sy += __shfl_xor_sync(0xFFFFFFFFu, sy, off);
        sz += __shfl_xor_sync(0xFFFFFFFFu, sz, off);
    }

    if (l8 == 0 && p < num_pts) {
        const unsigned o = 3u * (unsigned)p;
        out[o + 0] = sx;
        out[o + 1] = sy;
        out[o + 2] = sz;
    }
}

// Generic fallback for oversized control tables (no packing possible).
__global__ __launch_bounds__(256)
void thb_eval_raw_kernel(const float* __restrict__ ctrl,
                         const float* __restrict__ phi,
                         const int*   __restrict__ jm,
                         const int*   __restrict__ cum,
                         float*       __restrict__ out,
                         int num_pts)
{
    const int warp = (int)((blockIdx.x * (unsigned)blockDim.x + threadIdx.x) >> 5);
    if (warp >= num_pts) return;
    const int lane = threadIdx.x & 31;

    const int start = (warp == 0) ? 0 : cum[warp - 1];
    const int end   = cum[warp];

    float sx = 0.f, sy = 0.f, sz = 0.f;
    for (int k = start + lane; k < end; k += 32) {
        const float w = phi[k];
        const float* c = ctrl + 3u * (unsigned)jm[k];
        sx = fmaf(w, c[0], sx);
        sy = fmaf(w, c[1], sy);
        sz = fmaf(w, c[2], sz);
    }

    #pragma unroll
    for (int off = 16; off > 0; off >>= 1) {
        sx += __shfl_xor_sync(0xFFFFFFFFu, sx, off);
        sy += __shfl_xor_sync(0xFFFFFFFFu, sy, off);
        sz += __shfl_xor_sync(0xFFFFFFFFu, sz, off);
    }

    if (lane == 0) {
        const unsigned o = 3u * (unsigned)warp;
        out[o + 0] = sx;
        out[o + 1] = sy;
        out[o + 2] = sz;
    }
}

extern "C" void kernel_launch(void* const* d_in, const int* in_sizes, int n_in,
                              void* d_out, int out_size)
{
    const float* ctrl = (const float*)d_in[0];   // [N_CTRL, 3] f32
    const float* phi  = (const float*)d_in[1];   // [TOTAL] f32
    const int*   jm   = (const int*)d_in[2];     // [TOTAL] i32
    const int*   cum  = (const int*)d_in[3];     // [P] i32 inclusive row ends
    float*       out  = (float*)d_out;           // [P, 3] f32

    const int n_ctrl  = in_sizes[0] / 3;
    const int num_pts = in_sizes[3];

    if (n_ctrl <= MAX_CTRL) {
        pack_ctrl_kernel<<<(n_ctrl + 255) / 256, 256>>>(ctrl, n_ctrl);
        // 4 points/warp, 4 warps/block -> 16 points per block (validated optimum)
        const int blocks = (num_pts + 15) / 16;
        thb_eval_packed_kernel<<<blocks, 128>>>(phi, jm, cum, out, num_pts);
    } else {
        const int threads = 256;
        const long long total_threads = (long long)num_pts * 32;
        const int blocks = (int)((total_threads + threads - 1) / threads);
        thb_eval_raw_kernel<<<blocks, threads>>>(ctrl, phi, jm, cum, out, num_pts);
    }
}